// round 9
// baseline (speedup 1.0000x reference)
#include <cuda_runtime.h>
#include <cstdint>

#define MQ   32000
#define HN   32
#define CC   64
#define KK   15
#define COUTN 120

typedef unsigned long long ull;

// scratch
__device__ float  g_mod[(size_t)MQ * COUTN];   // sigmoid(mod), (M,120)
__device__ float4 g_pts4[MQ];                   // padded s_pts

// ---------------- f32x2 packed helpers (sm_103a) ----------------
__device__ __forceinline__ ull pack2(float a, float b) {
    ull r; asm("mov.b64 %0,{%1,%2};" : "=l"(r) : "f"(a), "f"(b)); return r;
}
__device__ __forceinline__ void unpack2(ull v, float& a, float& b) {
    asm("mov.b64 {%0,%1},%2;" : "=f"(a), "=f"(b) : "l"(v));
}
__device__ __forceinline__ ull fma2(ull a, ull b, ull c) {
    ull d; asm("fma.rn.f32x2 %0,%1,%2,%3;" : "=l"(d) : "l"(a), "l"(b), "l"(c)); return d;
}
__device__ __forceinline__ ull mul2(ull a, ull b) {
    ull d; asm("mul.rn.f32x2 %0,%1,%2;" : "=l"(d) : "l"(a), "l"(b)); return d;
}
__device__ __forceinline__ ull add2(ull a, ull b) {
    ull d; asm("add.rn.f32x2 %0,%1,%2;" : "=l"(d) : "l"(a), "l"(b)); return d;
}

// ---------------------------------------------------------------------------
// mlp_kernel v4: register-blocked GEMM + fused s_pts repack.
// Layer-2 weights staged PRE-DUPLICATED as (w,w) ull pairs -> no dup MOVs.
// smem bytes: Xtp 34304 + w1s 16384 + w2d 61440 + b1s 256 = 112384 (2 blk/SM)
// ---------------------------------------------------------------------------
#define XSTR 67
__global__ __launch_bounds__(256, 2) void mlp_kernel(
    const float* __restrict__ X,
    const float* __restrict__ w1,
    const float* __restrict__ b1,
    const float* __restrict__ w2,
    const float* __restrict__ s_pts)
{
    extern __shared__ char smc[];
    ull*   Xtp = reinterpret_cast<ull*>(smc);                    // 4288 ull
    float* w1s = reinterpret_cast<float*>(smc + 34304);          // 4096 f
    ull*   w2d = reinterpret_cast<ull*>(smc + 34304 + 16384);    // 7680 ull (dup)
    float* b1s = reinterpret_cast<float*>(smc + 112128);         // 64 f

    const int tid  = threadIdx.x;
    const int cg   = tid & 15;
    const int rg   = tid >> 4;
    const int rg4  = rg * 4;
    const int base = blockIdx.x * 128;

    // prologue: repack this block's 128 s_pts rows into g_pts4
    {
        float* tmp = reinterpret_cast<float*>(smc);
        for (int i = tid; i < 384; i += 256) tmp[i] = s_pts[base * 3 + i];
        __syncthreads();
        if (tid < 128) {
            float4 v;
            v.x = tmp[tid*3+0]; v.y = tmp[tid*3+1]; v.z = tmp[tid*3+2]; v.w = 0.f;
            g_pts4[base + tid] = v;
        }
        __syncthreads();
    }

    for (int i = tid; i < 4096; i += 256) w1s[i] = w1[i];
    for (int i = tid; i < 7680; i += 256) { float v = w2[i]; w2d[i] = pack2(v, v); }
    if (tid < 64) b1s[tid] = b1[tid];
#pragma unroll
    for (int i = 0; i < 4; i++) {
        const int idx = tid + 256 * i;
        const int c4 = idx & 15, rp = idx >> 4;
        const float4 a = *reinterpret_cast<const float4*>(X + (size_t)(base + 2*rp    ) * 64 + c4*4);
        const float4 b = *reinterpret_cast<const float4*>(X + (size_t)(base + 2*rp + 1) * 64 + c4*4);
        Xtp[(c4*4+0)*XSTR + rp] = pack2(a.x, b.x);
        Xtp[(c4*4+1)*XSTR + rp] = pack2(a.y, b.y);
        Xtp[(c4*4+2)*XSTR + rp] = pack2(a.z, b.z);
        Xtp[(c4*4+3)*XSTR + rp] = pack2(a.w, b.w);
    }
    __syncthreads();

    // layer 1: 8 rows x 4 cols per thread
    const int j0 = cg * 4;
    ull acc[4][4];
#pragma unroll
    for (int p = 0; p < 4; p++)
#pragma unroll
        for (int q = 0; q < 4; q++) acc[p][q] = 0ull;

#pragma unroll 4
    for (int c = 0; c < 64; c++) {
        ull xp[4];
#pragma unroll
        for (int p = 0; p < 4; p++) xp[p] = Xtp[c*XSTR + rg4 + p];
        const float4 wv = *reinterpret_cast<const float4*>(&w1s[c*64 + j0]);
        const ull wd0 = pack2(wv.x, wv.x), wd1 = pack2(wv.y, wv.y);
        const ull wd2 = pack2(wv.z, wv.z), wd3 = pack2(wv.w, wv.w);
#pragma unroll
        for (int p = 0; p < 4; p++) {
            acc[p][0] = fma2(xp[p], wd0, acc[p][0]);
            acc[p][1] = fma2(xp[p], wd1, acc[p][1]);
            acc[p][2] = fma2(xp[p], wd2, acc[p][2]);
            acc[p][3] = fma2(xp[p], wd3, acc[p][3]);
        }
    }
    __syncthreads();

#pragma unroll
    for (int q = 0; q < 4; q++) {
        const float bq = b1s[j0 + q];
#pragma unroll
        for (int p = 0; p < 4; p++) {
            float lo, hi; unpack2(acc[p][q], lo, hi);
            lo += bq; hi += bq;
            lo = (lo >= 0.f) ? lo : 0.1f * lo;
            hi = (hi >= 0.f) ? hi : 0.1f * hi;
            Xtp[(j0 + q)*XSTR + rg4 + p] = pack2(lo, hi);
        }
    }
    __syncthreads();

    // layer 2: 8 rows x 8 cols per thread, duplicated weights via LDS.128
    if (cg < 15) {
        const int o0 = cg * 8;
        ull a2[4][8];
#pragma unroll
        for (int p = 0; p < 4; p++)
#pragma unroll
            for (int q = 0; q < 8; q++) a2[p][q] = 0ull;

#pragma unroll 2
        for (int j = 0; j < 64; j++) {
            ull xp[4];
#pragma unroll
            for (int p = 0; p < 4; p++) xp[p] = Xtp[j*XSTR + rg4 + p];
            const ull* wrow = w2d + j*120 + o0;
            const ulonglong2 wv0 = *reinterpret_cast<const ulonglong2*>(wrow);
            const ulonglong2 wv1 = *reinterpret_cast<const ulonglong2*>(wrow + 2);
            const ulonglong2 wv2 = *reinterpret_cast<const ulonglong2*>(wrow + 4);
            const ulonglong2 wv3 = *reinterpret_cast<const ulonglong2*>(wrow + 6);
            const ull wd[8] = { wv0.x, wv0.y, wv1.x, wv1.y, wv2.x, wv2.y, wv3.x, wv3.y };
#pragma unroll
            for (int p = 0; p < 4; p++)
#pragma unroll
                for (int q = 0; q < 8; q++)
                    a2[p][q] = fma2(xp[p], wd[q], a2[p][q]);
        }

#pragma unroll
        for (int p = 0; p < 4; p++) {
            const int r0 = base + rg*8 + 2*p;
            float s0[8], s1[8];
#pragma unroll
            for (int q = 0; q < 8; q++) {
                float lo, hi; unpack2(a2[p][q], lo, hi);
                s0[q] = 1.f / (1.f + __expf(-lo));
                s1[q] = 1.f / (1.f + __expf(-hi));
            }
            ull* r0p = reinterpret_cast<ull*>(g_mod + (size_t)r0 * 120 + o0);
            ull* r1p = reinterpret_cast<ull*>(g_mod + (size_t)(r0+1) * 120 + o0);
#pragma unroll
            for (int t = 0; t < 4; t++) {
                r0p[t] = pack2(s0[2*t], s0[2*t+1]);
                r1p[t] = pack2(s1[2*t], s1[2*t+1]);
            }
        }
    }
}

// ---------------------------------------------------------------------------
// kp_kernel v4: fused geometry + sparse gather with COMPACTION + x4 batching.
// Active neighbors compacted into shared via ballot prefix; counted loop
// issues 4 independent gathers per batch (invalid slots -> scale 0, exact).
// ---------------------------------------------------------------------------
__global__ __launch_bounds__(256) void kp_kernel(
    const float* __restrict__ q_pts,
    const float* __restrict__ s_feats,
    const int*   __restrict__ nidx,
    const float* __restrict__ kpts,
    const float* __restrict__ Wg,
    float* __restrict__ out)
{
    __shared__ float sW[15 * 72];    // padded stride 72
    __shared__ float skp[45];
    __shared__ float smod[8][120];
    __shared__ ull   sact[8][32];    // compacted (infl bits, (k<<26)|(ind<<6))

    const int tid  = threadIdx.x;
    const int wid  = tid >> 5;
    const int lane = tid & 31;
    const int m    = blockIdx.x * 8 + wid;
    const unsigned FULL = 0xffffffffu;

    for (int i = tid; i < 960; i += 256) sW[(i >> 6) * 72 + (i & 63)] = Wg[i];
    if (tid < 45) skp[tid] = kpts[tid];
    for (int i = lane; i < 120; i += 32) smod[wid][i] = g_mod[(size_t)m * 120 + i];

    // geometry: one neighbor per lane
    const int ind = nidx[m * HN + lane];
    const float qx = q_pts[m*3+0], qy = q_pts[m*3+1], qz = q_pts[m*3+2];
    float4 p = g_pts4[ind];
    const float nx = p.x - qx, ny = p.y - qy, nz = p.z - qz;
    float best = 3.4e38f; int bk = 0;
    __syncthreads();   // skp/sW/smod ready
#pragma unroll
    for (int k = 0; k < 15; k++) {
        float dx = nx - skp[k*3+0];
        float dy = ny - skp[k*3+1];
        float dz = nz - skp[k*3+2];
        float d2 = fmaf(dx, dx, fmaf(dy, dy, dz*dz));
        if (d2 < best) { best = d2; bk = k; }   // strict <: first-min like argmin
    }

    // compact active neighbors (infl > 0 <=> best < 1)
    const unsigned mask = __ballot_sync(FULL, best < 1.0f);
    const int n = __popc(mask);
    if (best < 1.0f) {
        const float infl = 1.0f - sqrtf(best);
        const unsigned pk = ((unsigned)bk << 26) | ((unsigned)ind << 6);
        const int pos = __popc(mask & ((1u << lane) - 1u));
        sact[wid][pos] = ((ull)__float_as_uint(infl) << 32) | pk;
    }
    __syncwarp();

    // counted sparse accumulation, batched x4 (independent loads first)
    const int c2 = lane << 1;
    ull acc0 = 0ull, acc1 = 0ull;
    for (int j = 0; j < n; j += 4) {
        ull f[4], w[4]; float sc[4];
#pragma unroll
        for (int u = 0; u < 4; u++) {
            const bool     v   = (j + u) < n;
            const ull      geo = sact[wid][v ? (j + u) : (n - 1)];
            const unsigned pkh = (unsigned)geo;
            const int      k   = pkh >> 26;
            const int      row = pkh & 0x03FFFFFF;
            f[u]  = *reinterpret_cast<const ull*>(s_feats + row + c2);
            w[u]  = *reinterpret_cast<const ull*>(&sW[k * 72 + c2]);
            const float s = v ? __uint_as_float((unsigned)(geo >> 32)) : 0.0f;
            sc[u] = smod[wid][(k << 3) + (lane >> 2)] * s;
        }
#pragma unroll
        for (int u = 0; u < 4; u++) {
            const ull t = mul2(w[u], pack2(sc[u], sc[u]));
            if (u & 1) acc1 = fma2(f[u], t, acc1);
            else       acc0 = fma2(f[u], t, acc0);
        }
    }
    *reinterpret_cast<ull*>(out + (size_t)m * 64 + c2) = add2(acc0, acc1);
}

// ---------------------------------------------------------------------------
extern "C" void kernel_launch(void* const* d_in, const int* in_sizes, int n_in,
                              void* d_out, int out_size)
{
    const float* q_pts   = (const float*)d_in[0];
    const float* s_pts   = (const float*)d_in[1];
    const float* s_feats = (const float*)d_in[2];
    const int*   nidx    = (const int*)  d_in[3];
    const float* kpts    = (const float*)d_in[4];
    const float* W       = (const float*)d_in[5];
    const float* w1      = (const float*)d_in[6];
    const float* b1      = (const float*)d_in[7];
    const float* w2      = (const float*)d_in[8];
    float* out = (float*)d_out;

    const int smem = 112384;
    static bool init = false;
    if (!init) {
        cudaFuncSetAttribute(mlp_kernel, cudaFuncAttributeMaxDynamicSharedMemorySize, smem);
        init = true;
    }

    mlp_kernel<<<250, 256, smem>>>(s_feats, w1, b1, w2, s_pts);
    kp_kernel<<<MQ / 8, 256>>>(q_pts, s_feats, nidx, kpts, W, out);
}

// round 11
// speedup vs baseline: 1.7498x; 1.7498x over previous
#include <cuda_runtime.h>
#include <cstdint>

#define MQ   32000
#define HN   32
#define CC   64
#define KK   15
#define COUTN 120

typedef unsigned long long ull;

// scratch
__device__ float  g_h[(size_t)MQ * CC];        // hidden layer, (M,64)
__device__ float4 g_pts4[MQ];                   // padded s_pts
__device__ ull    g_w2i[KK * 256];              // w2 interleaved for kp dots

// ---------------- f32x2 packed helpers (sm_103a) ----------------
__device__ __forceinline__ ull pack2(float a, float b) {
    ull r; asm("mov.b64 %0,{%1,%2};" : "=l"(r) : "f"(a), "f"(b)); return r;
}
__device__ __forceinline__ void unpack2(ull v, float& a, float& b) {
    asm("mov.b64 {%0,%1},%2;" : "=f"(a), "=f"(b) : "l"(v));
}
__device__ __forceinline__ ull fma2(ull a, ull b, ull c) {
    ull d; asm("fma.rn.f32x2 %0,%1,%2,%3;" : "=l"(d) : "l"(a), "l"(b), "l"(c)); return d;
}
__device__ __forceinline__ ull mul2(ull a, ull b) {
    ull d; asm("mul.rn.f32x2 %0,%1,%2;" : "=l"(d) : "l"(a), "l"(b)); return d;
}
__device__ __forceinline__ ull add2(ull a, ull b) {
    ull d; asm("add.rn.f32x2 %0,%1,%2;" : "=l"(d) : "l"(a), "l"(b)); return d;
}

// ---------------------------------------------------------------------------
// mlp_l1: h = leaky(X @ W1 + b1) only (layer 2 is computed sparsely in kp).
// v3 register-blocked structure: 256 thr, 128 rows/block, 250 blocks.
// Also: fused s_pts->float4 repack, and w2 -> g_w2i interleave (blocks 0..14).
// smem bytes: Xtp 34304 + w1s 16384 + b1s 256 = 50944
// ---------------------------------------------------------------------------
#define XSTR 67
__global__ __launch_bounds__(256, 2) void mlp_l1_kernel(
    const float* __restrict__ X,
    const float* __restrict__ w1,
    const float* __restrict__ b1,
    const float* __restrict__ w2,
    const float* __restrict__ s_pts)
{
    extern __shared__ __align__(16) char smc[];
    ull*   Xtp = reinterpret_cast<ull*>(smc);                 // 4288 ull
    float* w1s = reinterpret_cast<float*>(smc + 34304);       // 4096 f
    float* b1s = reinterpret_cast<float*>(smc + 50688);       // 64 f

    const int tid  = threadIdx.x;
    const int cg   = tid & 15;
    const int rg   = tid >> 4;
    const int rg4  = rg * 4;
    const int base = blockIdx.x * 128;

    // side job 1: repack this block's 128 s_pts rows into g_pts4
    {
        float* tmp = reinterpret_cast<float*>(smc);
        for (int i = tid; i < 384; i += 256) tmp[i] = s_pts[base * 3 + i];
        __syncthreads();
        if (tid < 128) {
            float4 v;
            v.x = tmp[tid*3+0]; v.y = tmp[tid*3+1]; v.z = tmp[tid*3+2]; v.w = 0.f;
            g_pts4[base + tid] = v;
        }
        __syncthreads();
    }

    // side job 2: blocks 0..14 build g_w2i[k][t][lane] = (w2[j][o], w2[j+1][o])
    // with j = (lane&3)*16 + 2t, o = k*8 + (lane>>2)
    if (blockIdx.x < KK) {
        const int k = blockIdx.x;
        const int t = tid >> 5, l = tid & 31;
        const int j = (l & 3) * 16 + 2 * t;
        const int o = k * 8 + (l >> 2);
        g_w2i[k * 256 + t * 32 + l] = pack2(w2[j * 120 + o], w2[(j + 1) * 120 + o]);
    }

    // stage weights + X transposed row-pair packed
    for (int i = tid; i < 4096; i += 256) w1s[i] = w1[i];
    if (tid < 64) b1s[tid] = b1[tid];
#pragma unroll
    for (int i = 0; i < 4; i++) {
        const int idx = tid + 256 * i;
        const int c4 = idx & 15, rp = idx >> 4;
        const float4 a = *reinterpret_cast<const float4*>(X + (size_t)(base + 2*rp    ) * 64 + c4*4);
        const float4 b = *reinterpret_cast<const float4*>(X + (size_t)(base + 2*rp + 1) * 64 + c4*4);
        Xtp[(c4*4+0)*XSTR + rp] = pack2(a.x, b.x);
        Xtp[(c4*4+1)*XSTR + rp] = pack2(a.y, b.y);
        Xtp[(c4*4+2)*XSTR + rp] = pack2(a.z, b.z);
        Xtp[(c4*4+3)*XSTR + rp] = pack2(a.w, b.w);
    }
    __syncthreads();

    // layer 1: 8 rows x 4 cols per thread
    const int j0 = cg * 4;
    ull acc[4][4];
#pragma unroll
    for (int p = 0; p < 4; p++)
#pragma unroll
        for (int q = 0; q < 4; q++) acc[p][q] = 0ull;

#pragma unroll 4
    for (int c = 0; c < 64; c++) {
        ull xp[4];
#pragma unroll
        for (int p = 0; p < 4; p++) xp[p] = Xtp[c*XSTR + rg4 + p];
        const float4 wv = *reinterpret_cast<const float4*>(&w1s[c*64 + j0]);
        const ull wd0 = pack2(wv.x, wv.x), wd1 = pack2(wv.y, wv.y);
        const ull wd2 = pack2(wv.z, wv.z), wd3 = pack2(wv.w, wv.w);
#pragma unroll
        for (int p = 0; p < 4; p++) {
            acc[p][0] = fma2(xp[p], wd0, acc[p][0]);
            acc[p][1] = fma2(xp[p], wd1, acc[p][1]);
            acc[p][2] = fma2(xp[p], wd2, acc[p][2]);
            acc[p][3] = fma2(xp[p], wd3, acc[p][3]);
        }
    }

    // bias + leaky, store h rows to global
#pragma unroll
    for (int p = 0; p < 4; p++) {
        const int r0 = base + rg*8 + 2*p;
        float4 v0, v1;
        float* v0p = &v0.x; float* v1p = &v1.x;
#pragma unroll
        for (int q = 0; q < 4; q++) {
            float lo, hi; unpack2(acc[p][q], lo, hi);
            const float bq = b1s[j0 + q];
            lo += bq; hi += bq;
            v0p[q] = (lo >= 0.f) ? lo : 0.1f * lo;
            v1p[q] = (hi >= 0.f) ? hi : 0.1f * hi;
        }
        *reinterpret_cast<float4*>(g_h + (size_t)r0 * 64 + j0)       = v0;
        *reinterpret_cast<float4*>(g_h + (size_t)(r0 + 1) * 64 + j0) = v1;
    }
}

// ---------------------------------------------------------------------------
// kp_kernel v5: geometry + sparse on-the-fly modulation + gather.
// Per active neighbor (k known), the needed mod[k*8+g] values are computed
// as h . w2 column dots (lane (g,p) does a 16-elem packed partial, butterfly
// reduce over 4 lanes, sigmoid). Gather loop = round-8 x4-batched version.
// All ull-accessed shared arrays are explicitly 16B-aligned (R10 crash fix).
// ---------------------------------------------------------------------------
__global__ __launch_bounds__(256) void kp_kernel(
    const float* __restrict__ q_pts,
    const float* __restrict__ s_feats,
    const int*   __restrict__ nidx,
    const float* __restrict__ kpts,
    const float* __restrict__ Wg,
    float* __restrict__ out)
{
    __shared__ __align__(16) float sW[15 * 72];       // padded stride 72
    __shared__ __align__(16) float sh[8][66];         // h row per warp (stride 264B, 8B-mult)
    __shared__ __align__(16) float skp[48];           // padded to 8B multiple
    __shared__ float smodv[8][32][8];                 // mod per active slot per group
    __shared__ __align__(16) ull   sact[8][32];       // compacted (infl, (k<<26)|(ind<<6))

    const int tid  = threadIdx.x;
    const int wid  = tid >> 5;
    const int lane = tid & 31;
    const int m    = blockIdx.x * 8 + wid;
    const unsigned FULL = 0xffffffffu;

    for (int i = tid; i < 960; i += 256) sW[(i >> 6) * 72 + (i & 63)] = Wg[i];
    if (tid < 45) skp[tid] = kpts[tid];
    // stage h row (coalesced LDG.64 per lane)
    *reinterpret_cast<ull*>(&sh[wid][lane * 2]) =
        *reinterpret_cast<const ull*>(g_h + (size_t)m * 64 + lane * 2);

    // geometry: one neighbor per lane
    const int ind = nidx[m * HN + lane];
    const float qx = q_pts[m*3+0], qy = q_pts[m*3+1], qz = q_pts[m*3+2];
    float4 p = g_pts4[ind];
    const float nx = p.x - qx, ny = p.y - qy, nz = p.z - qz;
    float best = 3.4e38f; int bk = 0;
    __syncthreads();
#pragma unroll
    for (int k = 0; k < 15; k++) {
        float dx = nx - skp[k*3+0];
        float dy = ny - skp[k*3+1];
        float dz = nz - skp[k*3+2];
        float d2 = fmaf(dx, dx, fmaf(dy, dy, dz*dz));
        if (d2 < best) { best = d2; bk = k; }   // strict <: first-min like argmin
    }

    // compact active neighbors (infl > 0 <=> best < 1)
    const unsigned mask = __ballot_sync(FULL, best < 1.0f);
    const int n = __popc(mask);
    if (best < 1.0f) {
        const float infl = 1.0f - sqrtf(best);
        const unsigned pk = ((unsigned)bk << 26) | ((unsigned)ind << 6);
        const int pos = __popc(mask & ((1u << lane) - 1u));
        sact[wid][pos] = ((ull)__float_as_uint(infl) << 32) | pk;
    }
    __syncwarp();

    // on-the-fly modulation for active neighbors.
    // lane = (g = lane>>2, p = lane&3): partial dot over h[16p..16p+16).
    const int pq = lane & 3;
    const int g8 = lane >> 2;
    const ull* hrow = reinterpret_cast<const ull*>(&sh[wid][pq * 16]);
    for (int j = 0; j < n; j++) {
        const int k = ((unsigned)sact[wid][j]) >> 26;
        const ull* wbase = g_w2i + k * 256 + lane;
        ull part = 0ull;
#pragma unroll
        for (int t = 0; t < 8; t++)
            part = fma2(hrow[t], __ldg(&wbase[t * 32]), part);
        float lo, hi; unpack2(part, lo, hi);
        float d = lo + hi;
        d += __shfl_xor_sync(FULL, d, 1);
        d += __shfl_xor_sync(FULL, d, 2);
        smodv[wid][j][g8] = 1.f / (1.f + __expf(-d));
    }
    __syncwarp();

    // counted sparse accumulation, batched x4 (independent loads first)
    const int c2 = lane << 1;
    ull acc0 = 0ull, acc1 = 0ull;
    for (int j = 0; j < n; j += 4) {
        ull f[4], w[4]; float sc[4];
#pragma unroll
        for (int u = 0; u < 4; u++) {
            const bool     v   = (j + u) < n;
            const int      idx = v ? (j + u) : (n - 1);
            const ull      geo = sact[wid][idx];
            const unsigned pkh = (unsigned)geo;
            const int      k   = pkh >> 26;
            const int      row = pkh & 0x03FFFFFF;
            f[u]  = *reinterpret_cast<const ull*>(s_feats + row + c2);
            w[u]  = *reinterpret_cast<const ull*>(&sW[k * 72 + c2]);
            const float s = v ? __uint_as_float((unsigned)(geo >> 32)) : 0.0f;
            sc[u] = smodv[wid][idx][g8] * s;
        }
#pragma unroll
        for (int u = 0; u < 4; u++) {
            const ull t = mul2(w[u], pack2(sc[u], sc[u]));
            if (u & 1) acc1 = fma2(f[u], t, acc1);
            else       acc0 = fma2(f[u], t, acc0);
        }
    }
    *reinterpret_cast<ull*>(out + (size_t)m * 64 + c2) = add2(acc0, acc1);
}

// ---------------------------------------------------------------------------
extern "C" void kernel_launch(void* const* d_in, const int* in_sizes, int n_in,
                              void* d_out, int out_size)
{
    const float* q_pts   = (const float*)d_in[0];
    const float* s_pts   = (const float*)d_in[1];
    const float* s_feats = (const float*)d_in[2];
    const int*   nidx    = (const int*)  d_in[3];
    const float* kpts    = (const float*)d_in[4];
    const float* W       = (const float*)d_in[5];
    const float* w1      = (const float*)d_in[6];
    const float* b1      = (const float*)d_in[7];
    const float* w2      = (const float*)d_in[8];
    float* out = (float*)d_out;

    const int smem = 50944;
    static bool init = false;
    if (!init) {
        cudaFuncSetAttribute(mlp_l1_kernel, cudaFuncAttributeMaxDynamicSharedMemorySize, smem);
        init = true;
    }

    mlp_l1_kernel<<<250, 256, smem>>>(s_feats, w1, b1, w2, s_pts);
    kp_kernel<<<MQ / 8, 256>>>(q_pts, s_feats, nidx, kpts, W, out);
}